// round 2
// baseline (speedup 1.0000x reference)
#include <cuda_runtime.h>
#include <math.h>

// ---------------- problem constants ----------------
#define Bb 2
#define Sb 1024
#define Hd 2048
#define NH 16
#define NOPE 128
#define ROPE 64
#define VD 128
#define QKD 192          // NOPE + ROPE
#define QLR 1536
#define KVLR 512
#define DATT 576         // KVLR + ROPE
#define MBS (Bb*Sb)      // 2048 rows of (b,s)

// ---------------- scratch (static device globals; no allocation) ----------------
__device__ float g_qa    [MBS * QLR];            // hidden @ w_qa^T
__device__ float g_qaln  [MBS * QLR];            // LN(qa)
__device__ float g_kva   [MBS * DATT];           // hidden @ w_kva^T
__device__ float g_q     [MBS * NH * QKD];       // qaln @ w_qb^T
__device__ float g_qattn [MBS * NH * DATT];      // [B,S,NH,576] = q_lat ++ rope(q_pe)
__device__ float g_kattn [MBS * DATT];           // [B,S,576]    = LN(kv_c) ++ rope(k_pe)
__device__ float g_scores[(size_t)Bb*NH*Sb*Sb];  // [B,NH,S,S]
__device__ float g_ctx   [MBS * NH * KVLR];      // [B,S,NH,512]
__device__ float g_outfl [MBS * NH * VD];        // [B,S,2048]

// ---------------- generic batched tiled SGEMM ----------------
// C[m,n] (+batch offsets) = sum_k A[m,k] * (TB ? B[n,k] : B[k,n])
// per-z operand offset:  off = (z / dX) * sXd + (z % mX) * sXm
#define BM 128
#define BN 128
#define BK 8

template<bool TB>
__global__ void gemm_k(const float* __restrict__ A, int lda, long long sAd, int dA, long long sAm, int mA,
                       const float* __restrict__ B, int ldb, long long sBd, int dB, long long sBm, int mB,
                       float*       __restrict__ C, int ldc, long long sCd, int dC, long long sCm, int mC,
                       int M, int N, int K)
{
    int z = blockIdx.z;
    const float* Ab = A + (size_t)(z / dA) * sAd + (size_t)(z % mA) * sAm;
    const float* Bp = B + (size_t)(z / dB) * sBd + (size_t)(z % mB) * sBm;
    float*       Cb = C + (size_t)(z / dC) * sCd + (size_t)(z % mC) * sCm;

    int mBase = blockIdx.y * BM;
    int nBase = blockIdx.x * BN;

    __shared__ float As[BK][BM];
    __shared__ float Bs[BK][BN];

    int tid = threadIdx.x;          // 0..255
    int tx  = tid & 15;             // N direction
    int ty  = tid >> 4;             // M direction

    float acc[8][8];
#pragma unroll
    for (int i = 0; i < 8; i++)
#pragma unroll
        for (int j = 0; j < 8; j++) acc[i][j] = 0.f;

    for (int k0 = 0; k0 < K; k0 += BK) {
        // ---- load A tile (transposed into smem) ----
        {
            int arow = tid >> 1;
            int acol = (tid & 1) * 4;
            float4 v = make_float4(0.f, 0.f, 0.f, 0.f);
            int gr = mBase + arow;
            if (gr < M)
                v = *(const float4*)(Ab + (size_t)gr * lda + k0 + acol);
            As[acol + 0][arow] = v.x;
            As[acol + 1][arow] = v.y;
            As[acol + 2][arow] = v.z;
            As[acol + 3][arow] = v.w;
        }
        // ---- load B tile ----
        if (TB) {
            int brow = tid >> 1;            // n within tile
            int bcol = (tid & 1) * 4;       // k within tile
            float4 v = make_float4(0.f, 0.f, 0.f, 0.f);
            int gn = nBase + brow;
            if (gn < N)
                v = *(const float4*)(Bp + (size_t)gn * ldb + k0 + bcol);
            Bs[bcol + 0][brow] = v.x;
            Bs[bcol + 1][brow] = v.y;
            Bs[bcol + 2][brow] = v.z;
            Bs[bcol + 3][brow] = v.w;
        } else {
            int brow = tid >> 5;            // k within tile (0..7)
            int bcol = (tid & 31) * 4;      // n within tile
            int gn = nBase + bcol;
            float4 v = make_float4(0.f, 0.f, 0.f, 0.f);
            if (gn + 3 < N) {
                v = *(const float4*)(Bp + (size_t)(k0 + brow) * ldb + gn);
            } else {
                const float* bp = Bp + (size_t)(k0 + brow) * ldb;
                if (gn + 0 < N) v.x = bp[gn + 0];
                if (gn + 1 < N) v.y = bp[gn + 1];
                if (gn + 2 < N) v.z = bp[gn + 2];
                if (gn + 3 < N) v.w = bp[gn + 3];
            }
            *(float4*)&Bs[brow][bcol] = v;
        }
        __syncthreads();

#pragma unroll
        for (int kk = 0; kk < BK; kk++) {
            float a[8], b[8];
            *(float4*)&a[0] = *(const float4*)&As[kk][ty * 8];
            *(float4*)&a[4] = *(const float4*)&As[kk][ty * 8 + 4];
            *(float4*)&b[0] = *(const float4*)&Bs[kk][tx * 8];
            *(float4*)&b[4] = *(const float4*)&Bs[kk][tx * 8 + 4];
#pragma unroll
            for (int i = 0; i < 8; i++)
#pragma unroll
                for (int j = 0; j < 8; j++)
                    acc[i][j] = fmaf(a[i], b[j], acc[i][j]);
        }
        __syncthreads();
    }

    // ---- store C ----
#pragma unroll
    for (int i = 0; i < 8; i++) {
        int gr = mBase + ty * 8 + i;
        if (gr >= M) continue;
        float* cp = Cb + (size_t)gr * ldc + nBase + tx * 8;
        int gc = nBase + tx * 8;
        if (gc + 7 < N) {
            *(float4*)(cp + 0) = make_float4(acc[i][0], acc[i][1], acc[i][2], acc[i][3]);
            *(float4*)(cp + 4) = make_float4(acc[i][4], acc[i][5], acc[i][6], acc[i][7]);
        } else {
#pragma unroll
            for (int j = 0; j < 8; j++)
                if (gc + j < N) cp[j] = acc[i][j];
        }
    }
}

// ---------------- LayerNorm over last dim (one block per row) ----------------
__global__ void ln_rows(const float* __restrict__ in, int ldin,
                        const float* __restrict__ w,
                        float* __restrict__ out, int ldout, int dim)
{
    int r = blockIdx.x;
    const float* x = in + (size_t)r * ldin;
    float* y = out + (size_t)r * ldout;
    __shared__ float red[256];
    int tid = threadIdx.x;

    float s = 0.f;
    for (int i = tid; i < dim; i += 256) s += x[i];
    red[tid] = s; __syncthreads();
    for (int o = 128; o > 0; o >>= 1) { if (tid < o) red[tid] += red[tid + o]; __syncthreads(); }
    float mean = red[0] / dim;
    __syncthreads();

    float v = 0.f;
    for (int i = tid; i < dim; i += 256) { float d = x[i] - mean; v += d * d; }
    red[tid] = v; __syncthreads();
    for (int o = 128; o > 0; o >>= 1) { if (tid < o) red[tid] += red[tid + o]; __syncthreads(); }
    float rstd = rsqrtf(red[0] / dim + 1e-5f);

    for (int i = tid; i < dim; i += 256)
        y[i] = (x[i] - mean) * rstd * w[i];
}

// ---------------- RoPE for k_pe: kva[:,512:576] -> kattn[:,512:576] ----------------
__global__ void rope_k(const float* __restrict__ cosb, const float* __restrict__ sinb)
{
    int r = blockIdx.x;          // (b*S+s)
    int i = threadIdx.x;         // 0..63
    const float* src = g_kva + (size_t)r * DATT + KVLR;
    float x = src[i];
    float other = src[(i < 32) ? (i + 32) : (i - 32)];
    float rot = (i < 32) ? -other : other;
    g_kattn[(size_t)r * DATT + KVLR + i] = x * cosb[r * ROPE + i] + rot * sinb[r * ROPE + i];
}

// ---------------- RoPE for q_pe: q[:,h*192+128:+64] -> qattn[:,h,512:576] ----------------
__global__ void rope_q(const float* __restrict__ cosb, const float* __restrict__ sinb)
{
    int bs = blockIdx.x >> 4;
    int h  = blockIdx.x & 15;
    int i  = threadIdx.x;        // 0..63
    const float* src = g_q + (size_t)bs * (NH * QKD) + h * QKD + NOPE;
    float x = src[i];
    float other = src[(i < 32) ? (i + 32) : (i - 32)];
    float rot = (i < 32) ? -other : other;
    g_qattn[(size_t)bs * (NH * DATT) + h * DATT + KVLR + i] =
        x * cosb[bs * ROPE + i] + rot * sinb[bs * ROPE + i];
}

// ---------------- causal softmax over scores rows (scale folded in) ----------------
__global__ void softmax_causal()
{
    int r = blockIdx.x;                       // (b*NH+h)*S + q
    int q = r & (Sb - 1);
    float* row = g_scores + (size_t)r * Sb;
    int n = q + 1;
    const float scale = 0.07216878364870323f; // 1/sqrt(192)
    __shared__ float red[256];
    int tid = threadIdx.x;

    float mx = -3.4e38f;
    for (int i = tid; i < n; i += 256) mx = fmaxf(mx, row[i] * scale);
    red[tid] = mx; __syncthreads();
    for (int o = 128; o > 0; o >>= 1) { if (tid < o) red[tid] = fmaxf(red[tid], red[tid + o]); __syncthreads(); }
    mx = red[0];
    __syncthreads();

    float s = 0.f;
    for (int i = tid; i < n; i += 256) {
        float e = expf(row[i] * scale - mx);
        row[i] = e;
        s += e;
    }
    red[tid] = s; __syncthreads();
    for (int o = 128; o > 0; o >>= 1) { if (tid < o) red[tid] += red[tid + o]; __syncthreads(); }
    float inv = 1.f / red[0];

    for (int i = tid; i < n; i += 256) row[i] *= inv;
    for (int i = n + tid; i < Sb; i += 256) row[i] = 0.f;
}

// ---------------- launch ----------------
extern "C" void kernel_launch(void* const* d_in, const int* in_sizes, int n_in,
                              void* d_out, int out_size)
{
    const float* hidden  = (const float*)d_in[0];
    const float* cosb    = (const float*)d_in[1];
    const float* sinb    = (const float*)d_in[2];
    const float* w_qa    = (const float*)d_in[3];
    const float* qalnw   = (const float*)d_in[4];
    const float* w_qb    = (const float*)d_in[5];
    const float* w_kva   = (const float*)d_in[6];
    const float* kvalnw  = (const float*)d_in[7];
    const float* W_UK_T  = (const float*)d_in[8];
    const float* W_UV    = (const float*)d_in[9];
    const float* w_o     = (const float*)d_in[10];
    float* out = (float*)d_out;

    float *p_qa, *p_qaln, *p_kva, *p_q, *p_qattn, *p_kattn, *p_sc, *p_ctx, *p_of;
    cudaGetSymbolAddress((void**)&p_qa,    g_qa);
    cudaGetSymbolAddress((void**)&p_qaln,  g_qaln);
    cudaGetSymbolAddress((void**)&p_kva,   g_kva);
    cudaGetSymbolAddress((void**)&p_q,     g_q);
    cudaGetSymbolAddress((void**)&p_qattn, g_qattn);
    cudaGetSymbolAddress((void**)&p_kattn, g_kattn);
    cudaGetSymbolAddress((void**)&p_sc,    g_scores);
    cudaGetSymbolAddress((void**)&p_ctx,   g_ctx);
    cudaGetSymbolAddress((void**)&p_of,    g_outfl);

    auto grid = [](int M, int N, int z) {
        return dim3((N + BN - 1) / BN, (M + BM - 1) / BM, z);
    };
    const int T = 256;

    // 1) qa = hidden @ w_qa^T            [2048,1536]
    gemm_k<true><<<grid(MBS, QLR, 1), T>>>(
        hidden, Hd, 0,1,0,1,  w_qa, Hd, 0,1,0,1,  p_qa, QLR, 0,1,0,1,  MBS, QLR, Hd);

    // 2) kva = hidden @ w_kva^T          [2048,576]
    gemm_k<true><<<grid(MBS, DATT, 1), T>>>(
        hidden, Hd, 0,1,0,1,  w_kva, Hd, 0,1,0,1,  p_kva, DATT, 0,1,0,1,  MBS, DATT, Hd);

    // 3) LN(qa)
    ln_rows<<<MBS, T>>>(p_qa, QLR, qalnw, p_qaln, QLR, QLR);

    // 4) LN(kv_c) -> kattn[:, :512]
    ln_rows<<<MBS, T>>>(p_kva, DATT, kvalnw, p_kattn, DATT, KVLR);

    // 5) rope(k_pe) -> kattn[:, 512:576]
    rope_k<<<MBS, 64>>>(cosb, sinb);

    // 6) q = qaln @ w_qb^T               [2048,3072]
    gemm_k<true><<<grid(MBS, NH * QKD, 1), T>>>(
        p_qaln, QLR, 0,1,0,1,  w_qb, QLR, 0,1,0,1,  p_q, NH * QKD, 0,1,0,1,  MBS, NH * QKD, QLR);

    // 7) rope(q_pe) -> qattn[:,:,512:576]
    rope_q<<<MBS * NH, 64>>>(cosb, sinb);

    // 8) q_lat: per head, q_nope @ W_UK_T[h] -> qattn[:,:,h,0:512]
    //    A: g_q, off = h*192, lda = 3072 ; B: W_UK_T + h*128*512, [128,512]
    gemm_k<false><<<grid(MBS, KVLR, NH), T>>>(
        p_q, NH * QKD, 0,1, QKD, NH,
        W_UK_T, KVLR, 0,1, (long long)NOPE * KVLR, NH,
        p_qattn, NH * DATT, 0,1, DATT, NH,
        MBS, KVLR, NOPE);

    // 9) scores: per (b,h), qattn[b,:,h,:] @ kattn[b]^T   [1024,1024], K=576
    gemm_k<true><<<grid(Sb, Sb, Bb * NH), T>>>(
        p_qattn, NH * DATT, (long long)Sb * NH * DATT, NH, DATT, NH,
        p_kattn, DATT, (long long)Sb * DATT, NH, 0, 1,
        p_sc, Sb, (long long)Sb * Sb, 1, 0, 1,
        Sb, Sb, DATT);

    // 10) causal softmax (scale folded)
    softmax_causal<<<Bb * NH * Sb, T>>>();

    // 11) ctx: per (b,h), p @ kv_c -> ctx[b,:,h,:]   [1024,512], K=1024
    gemm_k<false><<<grid(Sb, KVLR, Bb * NH), T>>>(
        p_sc, Sb, (long long)Sb * Sb, 1, 0, 1,
        p_kattn, DATT, (long long)Sb * DATT, NH, 0, 1,
        p_ctx, NH * KVLR, (long long)Sb * NH * KVLR, NH, KVLR, NH,
        Sb, KVLR, Sb);

    // 12) out: per (b,h), ctx @ W_UV[h] -> outflat[b,:,h*128:+128]   [1024,128], K=512
    gemm_k<false><<<grid(Sb, VD, Bb * NH), T>>>(
        p_ctx, NH * KVLR, (long long)Sb * NH * KVLR, NH, KVLR, NH,
        W_UV, VD, 0,1, (long long)KVLR * VD, NH,
        p_of, NH * VD, (long long)Sb * NH * VD, NH, VD, NH,
        Sb, VD, KVLR);

    // 13) final: outflat @ w_o^T -> d_out   [2048,2048]
    gemm_k<true><<<grid(MBS, Hd, 1), T>>>(
        p_of, NH * VD, 0,1,0,1,  w_o, NH * VD, 0,1,0,1,  out, Hd, 0,1,0,1,  MBS, Hd, NH * VD);
}

// round 3
// speedup vs baseline: 2.2252x; 2.2252x over previous
#include <cuda_runtime.h>
#include <math.h>
#include <stdint.h>

// ---------------- problem constants ----------------
#define Bb 2
#define Sb 1024
#define Hd 2048
#define NH 16
#define NOPE 128
#define ROPE 64
#define VD 128
#define QKD 192          // NOPE + ROPE
#define QLR 1536
#define KVLR 512
#define DATT 576         // KVLR + ROPE
#define MBS (Bb*Sb)      // 2048 rows of (b,s)

// ---------------- scratch ----------------
__device__ float g_qa    [MBS * QLR];
__device__ float g_qaln  [MBS * QLR];
__device__ float g_kva   [MBS * DATT];
__device__ float g_q     [MBS * NH * QKD];
__device__ float g_qattn [MBS * NH * DATT];
__device__ float g_kattn [MBS * DATT];
__device__ float g_scores[(size_t)Bb*NH*Sb*Sb];
__device__ float g_ctx   [MBS * NH * KVLR];
__device__ float g_outfl [MBS * NH * VD];

#define BM 128
#define BN 128
#define BKK 32

__device__ __forceinline__ uint32_t f2tf32(float f) {
    uint32_t u;
    asm("cvt.rna.tf32.f32 %0, %1;" : "=r"(u) : "f"(f));
    return u;
}

__device__ __forceinline__ void mma_tf32(float c[4], const uint32_t a[4], const uint32_t b[2]) {
    asm volatile(
        "mma.sync.aligned.m16n8k8.row.col.f32.tf32.tf32.f32 "
        "{%0,%1,%2,%3},{%4,%5,%6,%7},{%8,%9},{%0,%1,%2,%3};"
        : "+f"(c[0]), "+f"(c[1]), "+f"(c[2]), "+f"(c[3])
        : "r"(a[0]), "r"(a[1]), "r"(a[2]), "r"(a[3]), "r"(b[0]), "r"(b[1]));
}

// Batched tf32 tensor-core GEMM.
// C[m,n] = sum_k A[m,k] * (TB ? B[n,k] : B[k,n])
// per-z operand offset: off = (z / dX) * sXd + (z % mX) * sXm
// causal: skip blocks with bx > by (fully masked score tiles)
// trunck: limit K loop to mBase+BM (p rows are causal-zero past the diagonal)
// Requirements: M % 128 == 0, K % 32 == 0, N % 4 == 0 (all hold for this problem).
template<bool TB>
__global__ void __launch_bounds__(256, 2)
mma_gemm(const float* __restrict__ A, int lda, long long sAd, int dA, long long sAm, int mA,
         const float* __restrict__ B, int ldb, long long sBd, int dB, long long sBm, int mB,
         float*       __restrict__ C, int ldc, long long sCd, int dC, long long sCm, int mC,
         int M, int N, int K, int causal, int trunck)
{
    if (causal && (int)blockIdx.x > (int)blockIdx.y) return;

    const int z = blockIdx.z;
    const float* Ab = A + (size_t)(z / dA) * sAd + (size_t)(z % mA) * sAm;
    const float* Bp = B + (size_t)(z / dB) * sBd + (size_t)(z % mB) * sBm;
    float*       Cb = C + (size_t)(z / dC) * sCd + (size_t)(z % mC) * sCm;

    const int mBase = blockIdx.y * BM;
    const int nBase = blockIdx.x * BN;

    // fragment-shuffled smem:
    // As[m16(8)][ks(4)][lane(32)][reg(4)]   Bs[n8(16)][ks(4)][lane(32)][reg(2)]
    __shared__ uint32_t As[8 * 4 * 32 * 4];
    __shared__ uint32_t Bs[16 * 4 * 32 * 2];

    const int tid  = threadIdx.x;
    const int lane = tid & 31;
    const int warp = tid >> 5;
    const int wm   = warp & 1;   // 2 warps in M (64 rows each)
    const int wn   = warp >> 1;  // 4 warps in N (32 cols each)

    float acc[4][4][4];
#pragma unroll
    for (int i = 0; i < 4; i++)
#pragma unroll
        for (int j = 0; j < 4; j++)
#pragma unroll
            for (int r = 0; r < 4; r++) acc[i][j][r] = 0.f;

    int Ke = K;
    if (trunck) { int lim = mBase + BM; if (lim < Ke) Ke = lim; }

    for (int k0 = 0; k0 < Ke; k0 += BKK) {
        // ---- stage A tile [128 x 32] into fragment layout ----
#pragma unroll
        for (int p = 0; p < 4; p++) {
            int idx  = tid + p * 256;             // 0..1023 float4 slots
            int row  = idx >> 3;                  // 0..127
            int c4   = (idx & 7) * 4;             // 0..28
            float4 v = *(const float4*)(Ab + (size_t)(mBase + row) * lda + k0 + c4);
            int m16  = row >> 4;
            int r8   = (row >> 3) & 1;
            int lA   = (row & 7) << 2;
#pragma unroll
            for (int u = 0; u < 4; u++) {
                int c   = c4 + u;
                int ks  = c >> 3;
                int cc  = c & 7;
                int ln  = lA | (cc & 3);
                int rg  = ((cc >> 2) << 1) | r8;
                float fv = (u == 0) ? v.x : (u == 1) ? v.y : (u == 2) ? v.z : v.w;
                As[(((m16 << 2) + ks) << 7) + (ln << 2) + rg] = f2tf32(fv);
            }
        }
        // ---- stage B tile into fragment layout ----
        if (TB) {
#pragma unroll
            for (int p = 0; p < 4; p++) {
                int idx  = tid + p * 256;
                int nrow = idx >> 3;              // 0..127
                int c4   = (idx & 7) * 4;
                int gn   = nBase + nrow;
                float4 v = make_float4(0.f, 0.f, 0.f, 0.f);
                if (gn < N)
                    v = *(const float4*)(Bp + (size_t)gn * ldb + k0 + c4);
                int n8 = nrow >> 3;
                int g4 = (nrow & 7) << 2;
#pragma unroll
                for (int u = 0; u < 4; u++) {
                    int c  = c4 + u;
                    int ks = c >> 3;
                    int cc = c & 7;
                    int ln = g4 | (cc & 3);
                    int rg = cc >> 2;
                    float fv = (u == 0) ? v.x : (u == 1) ? v.y : (u == 2) ? v.z : v.w;
                    Bs[(((n8 << 2) + ks) << 6) + (ln << 1) + rg] = f2tf32(fv);
                }
            }
        } else {
#pragma unroll
            for (int p = 0; p < 4; p++) {
                int idx  = tid + p * 256;
                int krow = idx >> 5;              // 0..31
                int c4   = (idx & 31) * 4;        // 0..124
                int gn   = nBase + c4;
                float4 v = make_float4(0.f, 0.f, 0.f, 0.f);
                if (gn < N)                        // N % 4 == 0 -> whole float4 valid
                    v = *(const float4*)(Bp + (size_t)(k0 + krow) * ldb + gn);
                int ks = krow >> 3;
                int cc = krow & 7;
#pragma unroll
                for (int u = 0; u < 4; u++) {
                    int n  = c4 + u;
                    int n8 = n >> 3;
                    int ln = ((n & 7) << 2) | (cc & 3);
                    int rg = cc >> 2;
                    float fv = (u == 0) ? v.x : (u == 1) ? v.y : (u == 2) ? v.z : v.w;
                    Bs[(((n8 << 2) + ks) << 6) + (ln << 1) + rg] = f2tf32(fv);
                }
            }
        }
        __syncthreads();

        // ---- compute: 4 k-steps of 16 mmas ----
#pragma unroll
        for (int ks = 0; ks < 4; ks++) {
            uint32_t a[4][4];
            uint32_t b[4][2];
#pragma unroll
            for (int i = 0; i < 4; i++) {
                int m16 = (wm << 2) + i;
                *(uint4*)a[i] = *(const uint4*)&As[(((m16 << 2) + ks) << 7) + (lane << 2)];
            }
#pragma unroll
            for (int j = 0; j < 4; j++) {
                int n8 = (wn << 2) + j;
                *(uint2*)b[j] = *(const uint2*)&Bs[(((n8 << 2) + ks) << 6) + (lane << 1)];
            }
#pragma unroll
            for (int i = 0; i < 4; i++)
#pragma unroll
                for (int j = 0; j < 4; j++)
                    mma_tf32(acc[i][j], a[i], b[j]);
        }
        __syncthreads();
    }

    // ---- epilogue ----
    const int g   = lane >> 2;
    const int tig = lane & 3;
#pragma unroll
    for (int i = 0; i < 4; i++) {
        int r0 = mBase + (wm << 6) + (i << 4) + g;
#pragma unroll
        for (int j = 0; j < 4; j++) {
            int col = nBase + (wn << 5) + (j << 3) + (tig << 1);
            if (col < N) {
                *(float2*)(Cb + (size_t)r0 * ldc + col)       = make_float2(acc[i][j][0], acc[i][j][1]);
                *(float2*)(Cb + (size_t)(r0 + 8) * ldc + col) = make_float2(acc[i][j][2], acc[i][j][3]);
            }
        }
    }
}

// ---------------- LayerNorm over last dim ----------------
__global__ void ln_rows(const float* __restrict__ in, int ldin,
                        const float* __restrict__ w,
                        float* __restrict__ out, int ldout, int dim)
{
    int r = blockIdx.x;
    const float* x = in + (size_t)r * ldin;
    float* y = out + (size_t)r * ldout;
    __shared__ float red[256];
    int tid = threadIdx.x;

    float s = 0.f;
    for (int i = tid; i < dim; i += 256) s += x[i];
    red[tid] = s; __syncthreads();
    for (int o = 128; o > 0; o >>= 1) { if (tid < o) red[tid] += red[tid + o]; __syncthreads(); }
    float mean = red[0] / dim;
    __syncthreads();

    float v = 0.f;
    for (int i = tid; i < dim; i += 256) { float d = x[i] - mean; v += d * d; }
    red[tid] = v; __syncthreads();
    for (int o = 128; o > 0; o >>= 1) { if (tid < o) red[tid] += red[tid + o]; __syncthreads(); }
    float rstd = rsqrtf(red[0] / dim + 1e-5f);

    for (int i = tid; i < dim; i += 256)
        y[i] = (x[i] - mean) * rstd * w[i];
}

// ---------------- RoPE k_pe ----------------
__global__ void rope_k(const float* __restrict__ cosb, const float* __restrict__ sinb)
{
    int r = blockIdx.x;
    int i = threadIdx.x;
    const float* src = g_kva + (size_t)r * DATT + KVLR;
    float x = src[i];
    float other = src[(i < 32) ? (i + 32) : (i - 32)];
    float rot = (i < 32) ? -other : other;
    g_kattn[(size_t)r * DATT + KVLR + i] = x * cosb[r * ROPE + i] + rot * sinb[r * ROPE + i];
}

// ---------------- RoPE q_pe ----------------
__global__ void rope_q(const float* __restrict__ cosb, const float* __restrict__ sinb)
{
    int bs = blockIdx.x >> 4;
    int h  = blockIdx.x & 15;
    int i  = threadIdx.x;
    const float* src = g_q + (size_t)bs * (NH * QKD) + h * QKD + NOPE;
    float x = src[i];
    float other = src[(i < 32) ? (i + 32) : (i - 32)];
    float rot = (i < 32) ? -other : other;
    g_qattn[(size_t)bs * (NH * DATT) + h * DATT + KVLR + i] =
        x * cosb[bs * ROPE + i] + rot * sinb[bs * ROPE + i];
}

// ---------------- causal softmax (scale folded) ----------------
__global__ void softmax_causal()
{
    int r = blockIdx.x;
    int q = r & (Sb - 1);
    float* row = g_scores + (size_t)r * Sb;
    int n = q + 1;
    const float scale = 0.07216878364870323f; // 1/sqrt(192)
    __shared__ float red[256];
    int tid = threadIdx.x;

    float mx = -3.4e38f;
    for (int i = tid; i < n; i += 256) mx = fmaxf(mx, row[i] * scale);
    red[tid] = mx; __syncthreads();
    for (int o = 128; o > 0; o >>= 1) { if (tid < o) red[tid] = fmaxf(red[tid], red[tid + o]); __syncthreads(); }
    mx = red[0];
    __syncthreads();

    float s = 0.f;
    for (int i = tid; i < n; i += 256) {
        float e = expf(row[i] * scale - mx);
        row[i] = e;
        s += e;
    }
    red[tid] = s; __syncthreads();
    for (int o = 128; o > 0; o >>= 1) { if (tid < o) red[tid] += red[tid + o]; __syncthreads(); }
    float inv = 1.f / red[0];

    for (int i = tid; i < n; i += 256) row[i] *= inv;
    for (int i = n + tid; i < Sb; i += 256) row[i] = 0.f;
}

// ---------------- launch ----------------
extern "C" void kernel_launch(void* const* d_in, const int* in_sizes, int n_in,
                              void* d_out, int out_size)
{
    const float* hidden  = (const float*)d_in[0];
    const float* cosb    = (const float*)d_in[1];
    const float* sinb    = (const float*)d_in[2];
    const float* w_qa    = (const float*)d_in[3];
    const float* qalnw   = (const float*)d_in[4];
    const float* w_qb    = (const float*)d_in[5];
    const float* w_kva   = (const float*)d_in[6];
    const float* kvalnw  = (const float*)d_in[7];
    const float* W_UK_T  = (const float*)d_in[8];
    const float* W_UV    = (const float*)d_in[9];
    const float* w_o     = (const float*)d_in[10];
    float* out = (float*)d_out;

    float *p_qa, *p_qaln, *p_kva, *p_q, *p_qattn, *p_kattn, *p_sc, *p_ctx, *p_of;
    cudaGetSymbolAddress((void**)&p_qa,    g_qa);
    cudaGetSymbolAddress((void**)&p_qaln,  g_qaln);
    cudaGetSymbolAddress((void**)&p_kva,   g_kva);
    cudaGetSymbolAddress((void**)&p_q,     g_q);
    cudaGetSymbolAddress((void**)&p_qattn, g_qattn);
    cudaGetSymbolAddress((void**)&p_kattn, g_kattn);
    cudaGetSymbolAddress((void**)&p_sc,    g_scores);
    cudaGetSymbolAddress((void**)&p_ctx,   g_ctx);
    cudaGetSymbolAddress((void**)&p_of,    g_outfl);

    auto grid = [](int M, int N, int z) {
        return dim3((N + BN - 1) / BN, (M + BM - 1) / BM, z);
    };
    const int T = 256;

    // 1) qa = hidden @ w_qa^T            [2048,1536] K=2048
    mma_gemm<true><<<grid(MBS, QLR, 1), T>>>(
        hidden, Hd, 0,1,0,1,  w_qa, Hd, 0,1,0,1,  p_qa, QLR, 0,1,0,1,  MBS, QLR, Hd, 0, 0);

    // 2) kva = hidden @ w_kva^T          [2048,576] K=2048
    mma_gemm<true><<<grid(MBS, DATT, 1), T>>>(
        hidden, Hd, 0,1,0,1,  w_kva, Hd, 0,1,0,1,  p_kva, DATT, 0,1,0,1,  MBS, DATT, Hd, 0, 0);

    // 3) LN(qa)
    ln_rows<<<MBS, T>>>(p_qa, QLR, qalnw, p_qaln, QLR, QLR);

    // 4) LN(kv_c) -> kattn[:, :512]
    ln_rows<<<MBS, T>>>(p_kva, DATT, kvalnw, p_kattn, DATT, KVLR);

    // 5) rope(k_pe) -> kattn[:, 512:576]
    rope_k<<<MBS, 64>>>(cosb, sinb);

    // 6) q = qaln @ w_qb^T               [2048,3072] K=1536
    mma_gemm<true><<<grid(MBS, NH * QKD, 1), T>>>(
        p_qaln, QLR, 0,1,0,1,  w_qb, QLR, 0,1,0,1,  p_q, NH * QKD, 0,1,0,1,  MBS, NH * QKD, QLR, 0, 0);

    // 7) rope(q_pe) -> qattn[:,:,512:576]
    rope_q<<<MBS * NH, 64>>>(cosb, sinb);

    // 8) q_lat: per head, q_nope @ W_UK_T[h] -> qattn[:,:,h,0:512]  K=128
    mma_gemm<false><<<grid(MBS, KVLR, NH), T>>>(
        p_q, NH * QKD, 0,1, QKD, NH,
        W_UK_T, KVLR, 0,1, (long long)NOPE * KVLR, NH,
        p_qattn, NH * DATT, 0,1, DATT, NH,
        MBS, KVLR, NOPE, 0, 0);

    // 9) scores: per (b,h), qattn[b,:,h,:] @ kattn[b]^T   [1024,1024] K=576, causal skip
    mma_gemm<true><<<grid(Sb, Sb, Bb * NH), T>>>(
        p_qattn, NH * DATT, (long long)Sb * NH * DATT, NH, DATT, NH,
        p_kattn, DATT, (long long)Sb * DATT, NH, 0, 1,
        p_sc, Sb, (long long)Sb * Sb, 1, 0, 1,
        Sb, Sb, DATT, 1, 0);

    // 10) causal softmax
    softmax_causal<<<Bb * NH * Sb, T>>>();

    // 11) ctx: per (b,h), p @ kv_c       [1024,512] K truncated to diag
    mma_gemm<false><<<grid(Sb, KVLR, Bb * NH), T>>>(
        p_sc, Sb, (long long)Sb * Sb, 1, 0, 1,
        p_kattn, DATT, (long long)Sb * DATT, NH, 0, 1,
        p_ctx, NH * KVLR, (long long)Sb * NH * KVLR, NH, KVLR, NH,
        Sb, KVLR, Sb, 0, 1);

    // 12) out: per (b,h), ctx @ W_UV[h]  [1024,128] K=512
    mma_gemm<false><<<grid(Sb, VD, Bb * NH), T>>>(
        p_ctx, NH * KVLR, (long long)Sb * NH * KVLR, NH, KVLR, NH,
        W_UV, VD, 0,1, (long long)KVLR * VD, NH,
        p_of, NH * VD, (long long)Sb * NH * VD, NH, VD, NH,
        Sb, VD, KVLR, 0, 0);

    // 13) final: outflat @ w_o^T -> d_out   [2048,2048] K=2048
    mma_gemm<true><<<grid(MBS, Hd, 1), T>>>(
        p_of, NH * VD, 0,1,0,1,  w_o, NH * VD, 0,1,0,1,  out, Hd, 0,1,0,1,  MBS, Hd, NH * VD, 0, 0);
}

// round 5
// speedup vs baseline: 4.1201x; 1.8516x over previous
#include <cuda_runtime.h>
#include <math.h>
#include <stdint.h>

// ---------------- problem constants ----------------
#define Bb 2
#define Sb 1024
#define Hd 2048
#define NH 16
#define NOPE 128
#define ROPE 64
#define VD 128
#define QKD 192
#define QLR 1536
#define KVLR 512
#define DATT 576
#define MBS (Bb*Sb)

// ---------------- scratch ----------------
__device__ float g_qa    [MBS * QLR];
__device__ float g_qaln  [MBS * QLR];
__device__ float g_kva   [MBS * DATT];
__device__ float g_q     [MBS * NH * QKD];
__device__ float g_qattn [MBS * NH * DATT];
__device__ float g_kattn [MBS * DATT];
__device__ float g_scores[(size_t)Bb*NH*Sb*Sb];
__device__ float g_ctx   [MBS * NH * KVLR];
__device__ float g_outfl [MBS * NH * VD];
__device__ float g_wukT  [NH * KVLR * NOPE];   // [h][512][128]
__device__ float g_wuvT  [NH * VD * KVLR];     // [h][128][512]
__device__ float g_kcT   [Bb * KVLR * Sb];     // [b][512][1024]

// ---------------- helpers ----------------
__device__ __forceinline__ uint32_t su32(const void* p) {
    uint32_t a;
    asm("{ .reg .u64 t; cvta.to.shared.u64 t, %1; cvt.u32.u64 %0, t; }" : "=r"(a) : "l"(p));
    return a;
}
__device__ __forceinline__ uint32_t f2tf(float f) {
    uint32_t u; asm("cvt.rna.tf32.f32 %0, %1;" : "=r"(u) : "f"(f)); return u;
}
__device__ __forceinline__ void mma_tf32(float c[4], const uint32_t a[4], const uint32_t b[2]) {
    asm volatile(
        "mma.sync.aligned.m16n8k8.row.col.f32.tf32.tf32.f32 "
        "{%0,%1,%2,%3},{%4,%5,%6,%7},{%8,%9},{%0,%1,%2,%3};"
        : "+f"(c[0]), "+f"(c[1]), "+f"(c[2]), "+f"(c[3])
        : "r"(a[0]), "r"(a[1]), "r"(a[2]), "r"(a[3]), "r"(b[0]), "r"(b[1]));
}
#define CP_ASYNC16(dst, src, sz) \
    asm volatile("cp.async.cg.shared.global [%0], [%1], 16, %2;" \
                 :: "r"(dst), "l"(src), "r"(sz) : "memory")
#define CP_COMMIT() asm volatile("cp.async.commit_group;" ::: "memory")
#define CP_WAIT(n)  asm volatile("cp.async.wait_group %0;" :: "n"(n) : "memory")

// ---------------- tiled tf32 mma GEMM with cp.async double buffering --------
// C[m,n] = sum_k A[m,k] * B[n,k]  (A [M,K] row-major, B [N,K] row-major)
// batched via z offsets: off = (z / dX) * sXd + (z % mX) * sXm
// Requirements: M % 128 == 0, K % 32 == 0 (N arbitrary mod 2).
#define BM 128
#define BN 128
#define BKK 32
#define LDS_STRIDE 36                    // 32 + 4 pad: (4g+tig)%32 conflict-free
#define TILE_F (BM * LDS_STRIDE)         // floats per tile buffer

__global__ void __launch_bounds__(256, 2)
mma_gemm(const float* __restrict__ A, int lda, long long sAd, int dA, long long sAm, int mA,
         const float* __restrict__ B, int ldb, long long sBd, int dB, long long sBm, int mB,
         float*       __restrict__ C, int ldc, long long sCd, int dC, long long sCm, int mC,
         int M, int N, int K, int causal, int trunck)
{
    const int mBase = blockIdx.y * BM;
    const int nBase = blockIdx.x * BN;
    if (causal && nBase > mBase + BM - 1) return;

    extern __shared__ float sm[];                 // [A0][A1][B0][B1]
    float* Abuf = sm;
    float* Bbuf = sm + 2 * TILE_F;
    const uint32_t sAbase = su32(Abuf);
    const uint32_t sBbase = su32(Bbuf);

    const int z = blockIdx.z;
    const float* Ab = A + (size_t)(z / dA) * sAd + (size_t)(z % mA) * sAm;
    const float* Bp = B + (size_t)(z / dB) * sBd + (size_t)(z % mB) * sBm;
    float*       Cb = C + (size_t)(z / dC) * sCd + (size_t)(z % mC) * sCm;

    const int tid  = threadIdx.x;
    const int lane = tid & 31;
    const int warp = tid >> 5;
    const int wm   = warp & 1;    // 2 warps in M (64 rows)
    const int wn   = warp >> 1;   // 4 warps in N (32 cols)
    const int g    = lane >> 2;
    const int tig  = lane & 3;

    // precomputed per-thread copy coordinates (4 float4 per tile)
    const int crow = tid >> 1;           // 0..127
    const int cc4  = (tid & 1) * 4;      // 0 or 4  -> two threads cover 8 float4? no:
    // 256 threads x 4 iters = 1024 float4 slots; slot = tid + p*256
    // row = slot >> 3 (0..127), col4 = (slot & 7) * 4

    float acc[4][4][4];
#pragma unroll
    for (int i = 0; i < 4; i++)
#pragma unroll
        for (int j = 0; j < 4; j++)
#pragma unroll
            for (int r = 0; r < 4; r++) acc[i][j][r] = 0.f;

    int Ke = K;
    if (trunck) { int lim = mBase + BM; if (lim < Ke) Ke = lim; }
    const int nc = Ke / BKK;

    // ---- async copy of one k-chunk into buffer p ----
    auto copy_chunk = [&](int ci, int p) {
        const int k0 = ci * BKK;
        const uint32_t aD = sAbase + (uint32_t)p * TILE_F * 4;
        const uint32_t bD = sBbase + (uint32_t)p * TILE_F * 4;
#pragma unroll
        for (int q = 0; q < 4; q++) {
            int slot = tid + q * 256;
            int row  = slot >> 3;
            int c4   = (slot & 7) << 2;
            uint32_t soff = (uint32_t)(row * LDS_STRIDE + c4) * 4;
            // A rows always valid (M % 128 == 0)
            CP_ASYNC16(aD + soff, Ab + (size_t)(mBase + row) * lda + k0 + c4, 16);
            int gn = nBase + row;
            const float* bsrc = (gn < N) ? (Bp + (size_t)gn * ldb + k0 + c4) : Bp;
            int sz = (gn < N) ? 16 : 0;
            CP_ASYNC16(bD + soff, bsrc, sz);
        }
        CP_COMMIT();
    };

    copy_chunk(0, 0);

    for (int i = 0; i < nc; i++) {
        const int p = i & 1;
        if (i + 1 < nc) {
            copy_chunk(i + 1, p ^ 1);
            CP_WAIT(1);
        } else {
            CP_WAIT(0);
        }
        __syncthreads();

        const float* As = Abuf + p * TILE_F;
        const float* Bs = Bbuf + p * TILE_F;
#pragma unroll
        for (int ks = 0; ks < 4; ks++) {
            const int kc = ks * 8;
            uint32_t a[4][4], b[4][2];
#pragma unroll
            for (int ii = 0; ii < 4; ii++) {
                int r0 = wm * 64 + ii * 16 + g;
                a[ii][0] = f2tf(As[(r0)     * LDS_STRIDE + kc + tig]);
                a[ii][1] = f2tf(As[(r0 + 8) * LDS_STRIDE + kc + tig]);
                a[ii][2] = f2tf(As[(r0)     * LDS_STRIDE + kc + tig + 4]);
                a[ii][3] = f2tf(As[(r0 + 8) * LDS_STRIDE + kc + tig + 4]);
            }
#pragma unroll
            for (int jj = 0; jj < 4; jj++) {
                int n0 = wn * 32 + jj * 8 + g;
                b[jj][0] = f2tf(Bs[n0 * LDS_STRIDE + kc + tig]);
                b[jj][1] = f2tf(Bs[n0 * LDS_STRIDE + kc + tig + 4]);
            }
#pragma unroll
            for (int ii = 0; ii < 4; ii++)
#pragma unroll
                for (int jj = 0; jj < 4; jj++)
                    mma_tf32(acc[ii][jj], a[ii], b[jj]);
        }
        __syncthreads();
    }

    // ---- epilogue ----
#pragma unroll
    for (int i = 0; i < 4; i++) {
        int r0 = mBase + (wm << 6) + (i << 4) + g;
#pragma unroll
        for (int j = 0; j < 4; j++) {
            int col = nBase + (wn << 5) + (j << 3) + (tig << 1);
            if (col < N) {
                *(float2*)(Cb + (size_t)r0 * ldc + col)       = make_float2(acc[i][j][0], acc[i][j][1]);
                *(float2*)(Cb + (size_t)(r0 + 8) * ldc + col) = make_float2(acc[i][j][2], acc[i][j][3]);
            }
        }
    }
}

// ---------------- transpose: out[z][n][m] = in[z][m][n] ----------------
__global__ void transpose_k(const float* __restrict__ in, long long sIn, int ldin,
                            float* __restrict__ out, long long sOut, int ldout)
{
    __shared__ float t[32][33];
    const float* ib = in + (size_t)blockIdx.z * sIn;
    float* ob = out + (size_t)blockIdx.z * sOut;
    int x0 = blockIdx.x * 32, y0 = blockIdx.y * 32;
    int tx = threadIdx.x, ty = threadIdx.y;    // 32 x 8
#pragma unroll
    for (int j = 0; j < 32; j += 8)
        t[ty + j][tx] = ib[(size_t)(y0 + ty + j) * ldin + x0 + tx];
    __syncthreads();
#pragma unroll
    for (int j = 0; j < 32; j += 8)
        ob[(size_t)(x0 + ty + j) * ldout + y0 + tx] = t[tx][ty + j];
}

// ---------------- LayerNorm over last dim ----------------
__global__ void ln_rows(const float* __restrict__ in, int ldin,
                        const float* __restrict__ w,
                        float* __restrict__ out, int ldout, int dim)
{
    int r = blockIdx.x;
    const float* x = in + (size_t)r * ldin;
    float* y = out + (size_t)r * ldout;
    __shared__ float red[256];
    int tid = threadIdx.x;

    float s = 0.f;
    for (int i = tid; i < dim; i += 256) s += x[i];
    red[tid] = s; __syncthreads();
    for (int o = 128; o > 0; o >>= 1) { if (tid < o) red[tid] += red[tid + o]; __syncthreads(); }
    float mean = red[0] / dim;
    __syncthreads();

    float v = 0.f;
    for (int i = tid; i < dim; i += 256) { float d = x[i] - mean; v += d * d; }
    red[tid] = v; __syncthreads();
    for (int o = 128; o > 0; o >>= 1) { if (tid < o) red[tid] += red[tid + o]; __syncthreads(); }
    float rstd = rsqrtf(red[0] / dim + 1e-5f);

    for (int i = tid; i < dim; i += 256)
        y[i] = (x[i] - mean) * rstd * w[i];
}

// ---------------- RoPE k_pe ----------------
__global__ void rope_k(const float* __restrict__ cosb, const float* __restrict__ sinb)
{
    int r = blockIdx.x;
    int i = threadIdx.x;
    const float* src = g_kva + (size_t)r * DATT + KVLR;
    float x = src[i];
    float other = src[(i < 32) ? (i + 32) : (i - 32)];
    float rot = (i < 32) ? -other : other;
    g_kattn[(size_t)r * DATT + KVLR + i] = x * cosb[r * ROPE + i] + rot * sinb[r * ROPE + i];
}

// ---------------- RoPE q_pe ----------------
__global__ void rope_q(const float* __restrict__ cosb, const float* __restrict__ sinb)
{
    int bs = blockIdx.x >> 4;
    int h  = blockIdx.x & 15;
    int i  = threadIdx.x;
    const float* src = g_q + (size_t)bs * (NH * QKD) + h * QKD + NOPE;
    float x = src[i];
    float other = src[(i < 32) ? (i + 32) : (i - 32)];
    float rot = (i < 32) ? -other : other;
    g_qattn[(size_t)bs * (NH * DATT) + h * DATT + KVLR + i] =
        x * cosb[bs * ROPE + i] + rot * sinb[bs * ROPE + i];
}

// ---------------- causal softmax (scale folded, fill to next 128) ----------------
__global__ void softmax_causal()
{
    int r = blockIdx.x;
    int q = r & (Sb - 1);
    float* row = g_scores + (size_t)r * Sb;
    int n = q + 1;
    int nfill = ((q >> 7) + 1) << 7;          // ctx only reads k < this (trunc)
    const float scale = 0.07216878364870323f; // 1/sqrt(192)
    __shared__ float red[256];
    int tid = threadIdx.x;

    float mx = -3.4e38f;
    for (int i = tid; i < n; i += 256) mx = fmaxf(mx, row[i] * scale);
    red[tid] = mx; __syncthreads();
    for (int o = 128; o > 0; o >>= 1) { if (tid < o) red[tid] = fmaxf(red[tid], red[tid + o]); __syncthreads(); }
    mx = red[0];
    __syncthreads();

    float s = 0.f;
    for (int i = tid; i < n; i += 256) {
        float e = expf(row[i] * scale - mx);
        row[i] = e;
        s += e;
    }
    red[tid] = s; __syncthreads();
    for (int o = 128; o > 0; o >>= 1) { if (tid < o) red[tid] += red[tid + o]; __syncthreads(); }
    float inv = 1.f / red[0];

    for (int i = tid; i < n; i += 256) row[i] *= inv;
    for (int i = n + tid; i < nfill; i += 256) row[i] = 0.f;
}

// ---------------- launch ----------------
extern "C" void kernel_launch(void* const* d_in, const int* in_sizes, int n_in,
                              void* d_out, int out_size)
{
    const float* hidden  = (const float*)d_in[0];
    const float* cosb    = (const float*)d_in[1];
    const float* sinb    = (const float*)d_in[2];
    const float* w_qa    = (const float*)d_in[3];
    const float* qalnw   = (const float*)d_in[4];
    const float* w_qb    = (const float*)d_in[5];
    const float* w_kva   = (const float*)d_in[6];
    const float* kvalnw  = (const float*)d_in[7];
    const float* W_UK_T  = (const float*)d_in[8];
    const float* W_UV    = (const float*)d_in[9];
    const float* w_o     = (const float*)d_in[10];
    float* out = (float*)d_out;

    float *p_qa, *p_qaln, *p_kva, *p_q, *p_qattn, *p_kattn, *p_sc, *p_ctx, *p_of;
    float *p_wukT, *p_wuvT, *p_kcT;
    cudaGetSymbolAddress((void**)&p_qa,    g_qa);
    cudaGetSymbolAddress((void**)&p_qaln,  g_qaln);
    cudaGetSymbolAddress((void**)&p_kva,   g_kva);
    cudaGetSymbolAddress((void**)&p_q,     g_q);
    cudaGetSymbolAddress((void**)&p_qattn, g_qattn);
    cudaGetSymbolAddress((void**)&p_kattn, g_kattn);
    cudaGetSymbolAddress((void**)&p_sc,    g_scores);
    cudaGetSymbolAddress((void**)&p_ctx,   g_ctx);
    cudaGetSymbolAddress((void**)&p_of,    g_outfl);
    cudaGetSymbolAddress((void**)&p_wukT,  g_wukT);
    cudaGetSymbolAddress((void**)&p_wuvT,  g_wuvT);
    cudaGetSymbolAddress((void**)&p_kcT,   g_kcT);

    const int SMEM = 4 * TILE_F * 4;   // 73728 bytes
    cudaFuncSetAttribute(mma_gemm, cudaFuncAttributeMaxDynamicSharedMemorySize, SMEM);

    auto grid = [](int M, int N, int z) {
        return dim3((N + BN - 1) / BN, M / BM, z);
    };
    const int T = 256;

    // 1) qa = hidden @ w_qa^T   [2048,1536] K=2048
    mma_gemm<<<grid(MBS, QLR, 1), T, SMEM>>>(
        hidden, Hd, 0,1,0,1,  w_qa, Hd, 0,1,0,1,  p_qa, QLR, 0,1,0,1,  MBS, QLR, Hd, 0, 0);

    // 2) kva = hidden @ w_kva^T [2048,576] K=2048
    mma_gemm<<<grid(MBS, DATT, 1), T, SMEM>>>(
        hidden, Hd, 0,1,0,1,  w_kva, Hd, 0,1,0,1,  p_kva, DATT, 0,1,0,1,  MBS, DATT, Hd, 0, 0);

    // 3) LN(qa)
    ln_rows<<<MBS, 256>>>(p_qa, QLR, qalnw, p_qaln, QLR, QLR);

    // 4) LN(kv_c) -> kattn[:, :512]
    ln_rows<<<MBS, 256>>>(p_kva, DATT, kvalnw, p_kattn, DATT, KVLR);

    // 5) rope(k_pe)
    rope_k<<<MBS, 64>>>(cosb, sinb);

    // T1) W_UK_T [h][128][512] -> g_wukT [h][512][128]
    transpose_k<<<dim3(16, 4, NH), dim3(32, 8)>>>(
        W_UK_T, (long long)NOPE * KVLR, KVLR, p_wukT, (long long)KVLR * NOPE, NOPE);

    // T2) W_UV [h][512][128] -> g_wuvT [h][128][512]
    transpose_k<<<dim3(4, 16, NH), dim3(32, 8)>>>(
        W_UV, (long long)KVLR * VD, VD, p_wuvT, (long long)VD * KVLR, KVLR);

    // T3) kv_c [b][1024][512 of 576] -> g_kcT [b][512][1024]
    transpose_k<<<dim3(16, 32, Bb), dim3(32, 8)>>>(
        p_kattn, (long long)Sb * DATT, DATT, p_kcT, (long long)KVLR * Sb, Sb);

    // 6) q = qaln @ w_qb^T      [2048,3072] K=1536
    mma_gemm<<<grid(MBS, NH * QKD, 1), T, SMEM>>>(
        p_qaln, QLR, 0,1,0,1,  w_qb, QLR, 0,1,0,1,  p_q, NH * QKD, 0,1,0,1,  MBS, NH * QKD, QLR, 0, 0);

    // 7) rope(q_pe)
    rope_q<<<MBS * NH, 64>>>(cosb, sinb);

    // 8) q_lat: per h, q_nope @ wukT[h]^T -> qattn[:,:,h,0:512]  M=2048,N=512,K=128
    mma_gemm<<<grid(MBS, KVLR, NH), T, SMEM>>>(
        p_q, NH * QKD, 0,1, QKD, NH,
        p_wukT, NOPE, 0,1, (long long)KVLR * NOPE, NH,
        p_qattn, NH * DATT, 0,1, DATT, NH,
        MBS, KVLR, NOPE, 0, 0);

    // 9) scores: per (b,h), qattn @ kattn^T  [1024,1024] K=576, causal
    mma_gemm<<<grid(Sb, Sb, Bb * NH), T, SMEM>>>(
        p_qattn, NH * DATT, (long long)Sb * NH * DATT, NH, DATT, NH,
        p_kattn, DATT, (long long)Sb * DATT, NH, 0, 1,
        p_sc, Sb, (long long)Sb * Sb, 1, 0, 1,
        Sb, Sb, DATT, 1, 0);

    // 10) causal softmax
    softmax_causal<<<Bb * NH * Sb, 256>>>();

    // 11) ctx: per (b,h), p @ kcT[b]^T   [1024,512] K<=1024 trunc
    mma_gemm<<<grid(Sb, KVLR, Bb * NH), T, SMEM>>>(
        p_sc, Sb, (long long)Sb * Sb, 1, 0, 1,
        p_kcT, Sb, (long long)KVLR * Sb, NH, 0, 1,
        p_ctx, NH * KVLR, (long long)Sb * NH * KVLR, NH, KVLR, NH,
        Sb, KVLR, Sb, 0, 1);

    // 12) out: per (b,h), ctx @ wuvT[h]^T  [1024,128] K=512
    mma_gemm<<<grid(Sb, VD, Bb * NH), T, SMEM>>>(
        p_ctx, NH * KVLR, (long long)Sb * NH * KVLR, NH, KVLR, NH,
        p_wuvT, KVLR, 0,1, (long long)VD * KVLR, NH,
        p_of, NH * VD, (long long)Sb * NH * VD, NH, VD, NH,
        Sb, VD, KVLR, 0, 0);

    // 13) final: outflat @ w_o^T -> d_out  [2048,2048] K=2048
    mma_gemm<<<grid(MBS, Hd, 1), T, SMEM>>>(
        p_of, NH * VD, 0,1,0,1,  w_o, NH * VD, 0,1,0,1,  out, Hd, 0,1,0,1,  MBS, Hd, NH * VD, 0, 0);
}